// round 5
// baseline (speedup 1.0000x reference)
#include <cuda_runtime.h>
#include <cstdint>

#define Bq 2
#define Tq 1024
#define Eq 1024
#define Hq 16
#define Dq 64
#define Lq 6
#define FFq 4096
#define Vq 32000

// ---------------- scratch (device globals; no runtime allocation) ----------
__device__ float g_x [Bq*Tq*Eq];
__device__ float g_h [Bq*Tq*Eq];
__device__ float g_q [Bq*Tq*Eq];
__device__ float g_k [Bq*Tq*Eq];
__device__ float g_v [Bq*Tq*Eq];
__device__ float g_o [Bq*Tq*Eq];
__device__ float g_ff[Bq*Tq*FFq];

// ---------------- block reductions (256 threads) ----------------------------
__device__ __forceinline__ float block_reduce_sum(float v) {
    __shared__ float sh[8];
    #pragma unroll
    for (int o = 16; o > 0; o >>= 1) v += __shfl_xor_sync(0xffffffffu, v, o);
    int lane = threadIdx.x & 31, w = threadIdx.x >> 5;
    if (lane == 0) sh[w] = v;
    __syncthreads();
    float r = (lane < 8) ? sh[lane] : 0.f;
    #pragma unroll
    for (int o = 4; o > 0; o >>= 1) r += __shfl_xor_sync(0xffffffffu, r, o);
    r = __shfl_sync(0xffffffffu, r, 0);
    __syncthreads();
    return r;
}

// ---------------- embedding --------------------------------------------------
__global__ __launch_bounds__(256) void embed_kernel(
    const int* __restrict__ idx, const float* __restrict__ tok_w,
    const float* __restrict__ pos, float* __restrict__ x)
{
    int i = blockIdx.x * 256 + threadIdx.x;          // over B*T*E/4 float4s
    const int E4 = Eq / 4;
    int e4 = i % E4;
    int bt = i / E4;
    int t  = bt % Tq;
    int tok = idx[bt];
    float4 tw = ((const float4*)tok_w)[(int64_t)tok * E4 + e4];
    float4 pe = ((const float4*)pos)[(int64_t)t * E4 + e4];
    ((float4*)x)[i] = make_float4(tw.x + pe.x, tw.y + pe.y, tw.z + pe.z, tw.w + pe.w);
}

// ---------------- layernorm (one block per row of E=1024) -------------------
__global__ __launch_bounds__(256) void ln_kernel(
    const float* __restrict__ x, float* __restrict__ y,
    const float* __restrict__ s, const float* __restrict__ b)
{
    int row = blockIdx.x;
    int tid = threadIdx.x;
    const float4* xr = (const float4*)(x + (int64_t)row * Eq);
    float4 v = xr[tid];
    float tot = block_reduce_sum(v.x + v.y + v.z + v.w);
    float mean = tot * (1.f / Eq);
    float dx = v.x - mean, dy = v.y - mean, dz = v.z - mean, dw = v.w - mean;
    float tot2 = block_reduce_sum(dx*dx + dy*dy + dz*dz + dw*dw);
    float inv = rsqrtf(tot2 * (1.f / Eq) + 1e-5f);
    float4 sv = ((const float4*)s)[tid];
    float4 bv = ((const float4*)b)[tid];
    float4 o;
    o.x = dx * inv * sv.x + bv.x;
    o.y = dy * inv * sv.y + bv.y;
    o.z = dz * inv * sv.z + bv.z;
    o.w = dw * inv * sv.w + bv.w;
    ((float4*)(y + (int64_t)row * Eq))[tid] = o;
}

// ---------------- tf32 helpers -----------------------------------------------
__device__ __forceinline__ uint32_t f2tf(float f) {
    uint32_t u;
    asm("cvt.rna.tf32.f32 %0, %1;" : "=r"(u) : "f"(f));
    return u;
}

#define MMA_TF32(c, a, b)                                                     \
    asm volatile(                                                             \
        "mma.sync.aligned.m16n8k8.row.col.f32.tf32.tf32.f32 "                 \
        "{%0,%1,%2,%3}, {%4,%5,%6,%7}, {%8,%9}, {%0,%1,%2,%3};"               \
        : "+f"(c[0]), "+f"(c[1]), "+f"(c[2]), "+f"(c[3])                      \
        : "r"(a[0]), "r"(a[1]), "r"(a[2]), "r"(a[3]), "r"(b[0]), "r"(b[1]))

#define MMA_TF32_V(c, av, bv)                                                 \
    asm volatile(                                                             \
        "mma.sync.aligned.m16n8k8.row.col.f32.tf32.tf32.f32 "                 \
        "{%0,%1,%2,%3}, {%4,%5,%6,%7}, {%8,%9}, {%0,%1,%2,%3};"               \
        : "+f"(c[0]), "+f"(c[1]), "+f"(c[2]), "+f"(c[3])                      \
        : "r"(av.x), "r"(av.y), "r"(av.z), "r"(av.w), "r"(bv.x), "r"(bv.y))

// ---------------- flash attention (causal, D=64) -----------------------------
// One block = one (b, h, 128-row q tile). 256 threads = 8 warps, each warp
// owns a 16-row slab. S kept in registers; online softmax; P staged via smem
// as tf32; O accumulated in fp32 registers. Never materializes T x T.
#define FL_SMEM_WORDS (8448 + 8448 + 8704 + 16896)

__global__ void __launch_bounds__(256, 1) flash_kernel(
    const float* __restrict__ q, const float* __restrict__ k,
    const float* __restrict__ v, float* __restrict__ o)
{
    extern __shared__ uint32_t dsm[];
    uint32_t* Qs = dsm;             // [64][132]
    uint32_t* Ks = Qs + 8448;       // [64][132]
    uint32_t* Vs = Ks + 8448;       // [128][68]
    uint32_t* Ps = Vs + 8704;       // [128][132]

    int bh = blockIdx.y;
    int b  = bh >> 4, hh = bh & 15;
    int qi = (int)gridDim.x - 1 - blockIdx.x;   // heavy tiles first
    int q0 = qi * 128;

    const float* qbase = q + (int64_t)b * Tq * Eq + hh * Dq;
    const float* kbase = k + (int64_t)b * Tq * Eq + hh * Dq;
    const float* vbase = v + (int64_t)b * Tq * Eq + hh * Dq;
    float*       obase = o + (int64_t)b * Tq * Eq + hh * Dq;

    int tid = threadIdx.x, warp = tid >> 5, lane = tid & 31;
    int g = lane >> 2, t = lane & 3;
    int m0 = warp * 16;

    // ---- load Q tile (once) ----
    {
        int mrow = tid >> 4;
        int d4   = (tid & 15) * 4;
        #pragma unroll
        for (int it = 0; it < 8; it++) {
            int m = mrow + it * 16;
            float4 qv = *(const float4*)(qbase + (int64_t)(q0 + m) * Eq + d4);
            Qs[(d4 + 0) * 132 + m] = f2tf(qv.x);
            Qs[(d4 + 1) * 132 + m] = f2tf(qv.y);
            Qs[(d4 + 2) * 132 + m] = f2tf(qv.z);
            Qs[(d4 + 3) * 132 + m] = f2tf(qv.w);
        }
    }

    float m_run0 = -1e30f, m_run1 = -1e30f;
    float l_run0 = 0.f,    l_run1 = 0.f;
    float oacc[8][4];
    #pragma unroll
    for (int nj = 0; nj < 8; nj++)
        #pragma unroll
        for (int e = 0; e < 4; e++) oacc[nj][e] = 0.f;

    int r0 = q0 + m0 + g, r1 = r0 + 8;

    for (int jt = 0; jt <= qi; jt++) {
        int kv0 = jt * 128;
        __syncthreads();
        // ---- load K, V tiles ----
        {
            int nrow = tid >> 4;
            int d4   = (tid & 15) * 4;
            #pragma unroll
            for (int it = 0; it < 8; it++) {
                int n = nrow + it * 16;
                float4 kv_ = *(const float4*)(kbase + (int64_t)(kv0 + n) * Eq + d4);
                Ks[(d4 + 0) * 132 + n] = f2tf(kv_.x);
                Ks[(d4 + 1) * 132 + n] = f2tf(kv_.y);
                Ks[(d4 + 2) * 132 + n] = f2tf(kv_.z);
                Ks[(d4 + 3) * 132 + n] = f2tf(kv_.w);
                float4 vv = *(const float4*)(vbase + (int64_t)(kv0 + n) * Eq + d4);
                Vs[n * 68 + d4 + 0] = f2tf(vv.x);
                Vs[n * 68 + d4 + 1] = f2tf(vv.y);
                Vs[n * 68 + d4 + 2] = f2tf(vv.z);
                Vs[n * 68 + d4 + 3] = f2tf(vv.w);
            }
        }
        __syncthreads();

        // ---- S = Q @ K^T for this warp's 16-row slab (16 x 128) ----
        float sacc[16][4];
        #pragma unroll
        for (int j = 0; j < 16; j++)
            #pragma unroll
            for (int e = 0; e < 4; e++) sacc[j][e] = 0.f;

        #pragma unroll
        for (int kb = 0; kb < 8; kb++) {
            uint32_t af[4];
            af[0] = Qs[(kb * 8 + t    ) * 132 + m0 + g];
            af[1] = Qs[(kb * 8 + t    ) * 132 + m0 + g + 8];
            af[2] = Qs[(kb * 8 + t + 4) * 132 + m0 + g];
            af[3] = Qs[(kb * 8 + t + 4) * 132 + m0 + g + 8];
            #pragma unroll
            for (int j = 0; j < 16; j++) {
                uint32_t bf[2];
                bf[0] = Ks[(kb * 8 + t    ) * 132 + j * 8 + g];
                bf[1] = Ks[(kb * 8 + t + 4) * 132 + j * 8 + g];
                MMA_TF32(sacc[j], af, bf);
            }
        }

        // ---- scale + causal mask + row max ----
        float mx0 = -1e30f, mx1 = -1e30f;
        #pragma unroll
        for (int j = 0; j < 16; j++) {
            #pragma unroll
            for (int e = 0; e < 2; e++) {
                int c = kv0 + j * 8 + t * 2 + e;
                float s0 = sacc[j][e]     * 0.125f;
                float s1 = sacc[j][e + 2] * 0.125f;
                if (c > r0) s0 = -1e30f;
                if (c > r1) s1 = -1e30f;
                sacc[j][e]     = s0;
                sacc[j][e + 2] = s1;
                mx0 = fmaxf(mx0, s0);
                mx1 = fmaxf(mx1, s1);
            }
        }
        mx0 = fmaxf(mx0, __shfl_xor_sync(0xffffffffu, mx0, 1));
        mx0 = fmaxf(mx0, __shfl_xor_sync(0xffffffffu, mx0, 2));
        mx1 = fmaxf(mx1, __shfl_xor_sync(0xffffffffu, mx1, 1));
        mx1 = fmaxf(mx1, __shfl_xor_sync(0xffffffffu, mx1, 2));

        float mnew0 = fmaxf(m_run0, mx0);
        float mnew1 = fmaxf(m_run1, mx1);
        float f0 = __expf(m_run0 - mnew0);
        float f1 = __expf(m_run1 - mnew1);

        // ---- P = exp(S - m), write to smem (tf32), row sums ----
        float sum0 = 0.f, sum1 = 0.f;
        #pragma unroll
        for (int j = 0; j < 16; j++) {
            #pragma unroll
            for (int e = 0; e < 2; e++) {
                float p0 = __expf(sacc[j][e]     - mnew0);
                float p1 = __expf(sacc[j][e + 2] - mnew1);
                sum0 += p0;
                sum1 += p1;
                int krow = j * 8 + t * 2 + e;
                Ps[krow * 132 + m0 + g]     = f2tf(p0);
                Ps[krow * 132 + m0 + g + 8] = f2tf(p1);
            }
        }
        sum0 += __shfl_xor_sync(0xffffffffu, sum0, 1);
        sum0 += __shfl_xor_sync(0xffffffffu, sum0, 2);
        sum1 += __shfl_xor_sync(0xffffffffu, sum1, 1);
        sum1 += __shfl_xor_sync(0xffffffffu, sum1, 2);

        l_run0 = l_run0 * f0 + sum0;
        l_run1 = l_run1 * f1 + sum1;
        m_run0 = mnew0;
        m_run1 = mnew1;

        // ---- rescale O accumulator ----
        #pragma unroll
        for (int nj = 0; nj < 8; nj++) {
            oacc[nj][0] *= f0; oacc[nj][1] *= f0;
            oacc[nj][2] *= f1; oacc[nj][3] *= f1;
        }
        __syncwarp();

        // ---- O += P @ V  (K-dim = 128) ----
        #pragma unroll
        for (int kb = 0; kb < 16; kb++) {
            uint32_t af[4];
            af[0] = Ps[(kb * 8 + t    ) * 132 + m0 + g];
            af[1] = Ps[(kb * 8 + t    ) * 132 + m0 + g + 8];
            af[2] = Ps[(kb * 8 + t + 4) * 132 + m0 + g];
            af[3] = Ps[(kb * 8 + t + 4) * 132 + m0 + g + 8];
            #pragma unroll
            for (int nj = 0; nj < 8; nj++) {
                uint32_t bf[2];
                bf[0] = Vs[(kb * 8 + t    ) * 68 + nj * 8 + g];
                bf[1] = Vs[(kb * 8 + t + 4) * 68 + nj * 8 + g];
                MMA_TF32(oacc[nj], af, bf);
            }
        }
    }

    // ---- epilogue: normalize and store ----
    float inv0 = 1.f / l_run0;
    float inv1 = 1.f / l_run1;
    #pragma unroll
    for (int nj = 0; nj < 8; nj++) {
        int c = nj * 8 + t * 2;
        *(float2*)(obase + (int64_t)r0 * Eq + c) =
            make_float2(oacc[nj][0] * inv0, oacc[nj][1] * inv0);
        *(float2*)(obase + (int64_t)r1 * Eq + c) =
            make_float2(oacc[nj][2] * inv1, oacc[nj][3] * inv1);
    }
}

// ---------------- TF32 tensor-core GEMM (fragment-order smem) ----------------
// C = alpha * A @ B (+bias[n]) (+resid) (ReLU optional)
// A: M x K row-major (lda). B: K x N row-major (ldb).
// Block tile BM x 128 x 16, 8 warps (BM/2 x 32 warp tiles).
// Smem holds m16n8k8 fragments directly:
//   As[buf][mtile][kb][lane][4]  -> one LDS.128 = full A fragment
//   Bs[buf][ntile][kb][lane][2]  -> one LDS.64  = full B fragment
// A element (m,k): mtile=m>>4, kb=k>>3, lane=(m&7)*4+(k&3),
//                  slot=((m>>3)&1) + 2*((k>>2)&1)
// B element (k,n): ntile=n>>3, kb=k>>3, lane=(n&7)*4+(k&3), slot=(k>>2)&1
template<int BM>
__global__ __launch_bounds__(256, 2) void gemm_tc(
    const float* __restrict__ A, const float* __restrict__ Bm, float* __restrict__ C,
    int M, int N, int K, int lda, int ldb, int ldc,
    const float* __restrict__ bias, const float* __restrict__ resid,
    int relu, float alpha,
    const float* B1, float* C1, const float* B2, float* C2)
{
    constexpr int MT = BM / 16;        // m-tiles per block
    constexpr int II = BM / 32;        // i-tiles per warp
    __shared__ uint32_t As[2][MT][2][32][4];
    __shared__ uint32_t Bs[2][16][2][32][2];

    int zo = blockIdx.z;
    if (B1 && zo == 1) { Bm = B1; C = C1; }
    if (B2 && zo == 2) { Bm = B2; C = C2; }

    int row0 = blockIdx.y * BM;
    int col0 = blockIdx.x * 128;

    int tid  = threadIdx.x;
    int warp = tid >> 5, lane = tid & 31;
    int g = lane >> 2, t = lane & 3;
    int wMt = (warp & 1) * (MT / 2);   // warp m-tile offset
    int wNt = (warp >> 1) * 4;         // warp n-tile offset (32 cols)
    int wM = wMt * 16;
    int wN = wNt * 8;

    float acc[II][4][4];
    #pragma unroll
    for (int i = 0; i < II; i++)
        #pragma unroll
        for (int j = 0; j < 4; j++)
            #pragma unroll
            for (int e = 0; e < 4; e++) acc[i][j][e] = 0.f;

    const int aM  = tid >> 2;    // 0..63
    const int akq = tid & 3;     // 0..3
    constexpr int AIT = BM / 64; // A-load iterations

    float4 stA[AIT > 0 ? AIT : 1], stB[2];

    auto loadg = [&](int k0) {
        #pragma unroll
        for (int it = 0; it < AIT; it++) {
            int m = aM + it * 64;
            float4 v = make_float4(0.f, 0.f, 0.f, 0.f);
            if (row0 + m < M)
                v = *(const float4*)(A + (int64_t)(row0 + m) * lda + k0 + akq * 4);
            stA[it] = v;
        }
        #pragma unroll
        for (int it = 0; it < 2; it++) {
            float4 v = make_float4(0.f, 0.f, 0.f, 0.f);
            int n4 = tid & 31;
            int kk = (tid >> 5) + it * 8;
            int n  = col0 + n4 * 4;
            if (n + 3 < N)
                v = *(const float4*)(Bm + (int64_t)(k0 + kk) * ldb + n);
            stB[it] = v;
        }
    };

    auto stores = [&](int buf) {
        // A: thread has rows m=aM+it*64, k = akq*4 + c (c=0..3)
        #pragma unroll
        for (int it = 0; it < AIT; it++) {
            int m = aM + it * 64;
            int mtile = m >> 4;
            int gm = m & 7;
            int sM = (m >> 3) & 1;
            int kb = akq >> 1;
            int sK2 = (akq & 1) * 2;
            float vv[4] = {stA[it].x, stA[it].y, stA[it].z, stA[it].w};
            #pragma unroll
            for (int c = 0; c < 4; c++)
                As[buf][mtile][kb][gm * 4 + c][sM + sK2] = f2tf(vv[c]);
        }
        // B: thread has row k=kk, cols n = n4*4 + c
        #pragma unroll
        for (int it = 0; it < 2; it++) {
            int n4 = tid & 31;
            int kk = (tid >> 5) + it * 8;
            int kb = kk >> 3;
            int sK = (kk >> 2) & 1;
            int lk = kk & 3;
            float vv[4] = {stB[it].x, stB[it].y, stB[it].z, stB[it].w};
            #pragma unroll
            for (int c = 0; c < 4; c++) {
                int n = n4 * 4 + c;
                Bs[buf][n >> 3][kb][(n & 7) * 4 + lk][sK] = f2tf(vv[c]);
            }
        }
    };

    auto compute = [&](int buf) {
        #pragma unroll
        for (int ks = 0; ks < 2; ks++) {
            uint4 av[II];
            uint2 bv[4];
            #pragma unroll
            for (int i = 0; i < II; i++)
                av[i] = *(const uint4*)&As[buf][wMt + i][ks][lane][0];
            #pragma unroll
            for (int j = 0; j < 4; j++)
                bv[j] = *(const uint2*)&Bs[buf][wNt + j][ks][lane][0];
            #pragma unroll
            for (int i = 0; i < II; i++)
                #pragma unroll
                for (int j = 0; j < 4; j++)
                    MMA_TF32_V(acc[i][j], av[i], bv[j]);
        }
    };

    // pipeline: prologue
    loadg(0);
    stores(0);
    __syncthreads();

    int nit = K >> 4;
    int buf = 0;
    for (int itk = 1; itk < nit; itk++) {
        loadg(itk << 4);
        compute(buf);
        stores(buf ^ 1);
        __syncthreads();
        buf ^= 1;
    }
    compute(buf);

    // ---- epilogue ----
    #pragma unroll
    for (int i = 0; i < II; i++) {
        int r0 = row0 + wM + i * 16 + g;
        #pragma unroll
        for (int j = 0; j < 4; j++) {
            int c = col0 + wN + j * 8 + t * 2;
            if (c >= N) continue;
            #pragma unroll
            for (int half = 0; half < 2; half++) {
                int r = r0 + half * 8;
                if (r >= M) continue;
                float v0 = alpha * acc[i][j][half * 2 + 0];
                float v1 = alpha * acc[i][j][half * 2 + 1];
                if (bias) { v0 += bias[c]; v1 += bias[c + 1]; }
                if (resid) {
                    float2 rv = *(const float2*)(resid + (int64_t)r * ldc + c);
                    v0 += rv.x; v1 += rv.y;
                }
                if (relu) { v0 = fmaxf(v0, 0.f); v1 = fmaxf(v1, 0.f); }
                *(float2*)(C + (int64_t)r * ldc + c) = make_float2(v0, v1);
            }
        }
    }
}

// ---------------- host orchestration ----------------------------------------
static inline dim3 ggrid(int M, int N, int batch, int bm) {
    return dim3((unsigned)((N + 127) / 128), (unsigned)((M + bm - 1) / bm), (unsigned)batch);
}

extern "C" void kernel_launch(void* const* d_in, const int* in_sizes, int n_in,
                              void* d_out, int out_size)
{
    const int*   idx    = (const int*)  d_in[0];
    const float* tok_w  = (const float*)d_in[1];
    const float* pos    = (const float*)d_in[2];
    const float* ln1_s  = (const float*)d_in[3];
    const float* ln1_b  = (const float*)d_in[4];
    const float* wq     = (const float*)d_in[5];
    const float* wk     = (const float*)d_in[6];
    const float* wv     = (const float*)d_in[7];
    const float* wo     = (const float*)d_in[8];
    const float* bo     = (const float*)d_in[9];
    const float* ln2_s  = (const float*)d_in[10];
    const float* ln2_b  = (const float*)d_in[11];
    const float* w1     = (const float*)d_in[12];
    const float* b1     = (const float*)d_in[13];
    const float* w2     = (const float*)d_in[14];
    const float* b2     = (const float*)d_in[15];
    const float* lnf_s  = (const float*)d_in[16];
    const float* lnf_b  = (const float*)d_in[17];
    const float* head_w = (const float*)d_in[18];
    const float* head_b = (const float*)d_in[19];
    float* out = (float*)d_out;

    float *x, *h, *q, *k, *v, *o, *ff;
    cudaGetSymbolAddress((void**)&x,   g_x);
    cudaGetSymbolAddress((void**)&h,   g_h);
    cudaGetSymbolAddress((void**)&q,   g_q);
    cudaGetSymbolAddress((void**)&k,   g_k);
    cudaGetSymbolAddress((void**)&v,   g_v);
    cudaGetSymbolAddress((void**)&o,   g_o);
    cudaGetSymbolAddress((void**)&ff,  g_ff);

    const int M = Bq * Tq;                  // 2048
    const int flashSmem = FL_SMEM_WORDS * 4;
    cudaFuncSetAttribute(flash_kernel,
        cudaFuncAttributeMaxDynamicSharedMemorySize, flashSmem);

    // embedding
    embed_kernel<<<(M * Eq / 4 + 255) / 256, 256>>>(idx, tok_w, pos, x);

    for (int l = 0; l < Lq; l++) {
        const float* Wq = wq + (int64_t)l * Eq * Eq;
        const float* Wk = wk + (int64_t)l * Eq * Eq;
        const float* Wv = wv + (int64_t)l * Eq * Eq;
        const float* Wo = wo + (int64_t)l * Eq * Eq;
        const float* W1 = w1 + (int64_t)l * Eq * FFq;
        const float* W2 = w2 + (int64_t)l * FFq * Eq;

        // ln1
        ln_kernel<<<M, 256>>>(x, h, ln1_s + l * Eq, ln1_b + l * Eq);

        // fused q/k/v projections (z selects weight + output)
        gemm_tc<128><<<ggrid(M, Eq, 3, 128), 256>>>(h, Wq, q,
            M, Eq, Eq, Eq, Eq, Eq,
            nullptr, nullptr, 0, 1.0f,
            Wk, k, Wv, v);

        // fused flash attention: o = softmax(causal(qk^T/sqrt(d))) @ v
        flash_kernel<<<dim3(Tq / 128, Bq * Hq), 256, flashSmem>>>(q, k, v, o);

        // x = x + o @ Wo + bo
        gemm_tc<64><<<ggrid(M, Eq, 1, 64), 256>>>(o, Wo, x,
            M, Eq, Eq, Eq, Eq, Eq,
            bo + l * Eq, x, 0, 1.0f,
            nullptr, nullptr, nullptr, nullptr);

        // ln2
        ln_kernel<<<M, 256>>>(x, h, ln2_s + l * Eq, ln2_b + l * Eq);

        // ff = relu(h @ W1 + b1)
        gemm_tc<128><<<ggrid(M, FFq, 1, 128), 256>>>(h, W1, ff,
            M, FFq, Eq, Eq, FFq, FFq,
            b1 + l * FFq, nullptr, 1, 1.0f,
            nullptr, nullptr, nullptr, nullptr);

        // x = x + ff @ W2 + b2
        gemm_tc<64><<<ggrid(M, Eq, 1, 64), 256>>>(ff, W2, x,
            M, Eq, FFq, FFq, Eq, Eq,
            b2 + l * Eq, x, 0, 1.0f,
            nullptr, nullptr, nullptr, nullptr);
    }

    // final layernorm
    ln_kernel<<<M, 256>>>(x, h, lnf_s, lnf_b);

    // logits = h @ head_w + head_b
    gemm_tc<128><<<ggrid(M, Vq, 1, 128), 256>>>(h, head_w, out,
        M, Vq, Eq, Eq, Vq, Vq,
        head_b, nullptr, 0, 1.0f,
        nullptr, nullptr, nullptr, nullptr);
}

// round 6
// speedup vs baseline: 2.3270x; 2.3270x over previous
#include <cuda_runtime.h>
#include <cstdint>

#define Bq 2
#define Tq 1024
#define Eq 1024
#define Hq 16
#define Dq 64
#define Lq 6
#define FFq 4096
#define Vq 32000

// ---------------- scratch (device globals; no runtime allocation) ----------
__device__ float g_x [Bq*Tq*Eq];
__device__ float g_h [Bq*Tq*Eq];
__device__ float g_q [Bq*Tq*Eq];
__device__ float g_k [Bq*Tq*Eq];
__device__ float g_v [Bq*Tq*Eq];
__device__ float g_o [Bq*Tq*Eq];
__device__ float g_ff[Bq*Tq*FFq];

// ---------------- block reductions (256 threads) ----------------------------
__device__ __forceinline__ float block_reduce_sum(float v) {
    __shared__ float sh[8];
    #pragma unroll
    for (int o = 16; o > 0; o >>= 1) v += __shfl_xor_sync(0xffffffffu, v, o);
    int lane = threadIdx.x & 31, w = threadIdx.x >> 5;
    if (lane == 0) sh[w] = v;
    __syncthreads();
    float r = (lane < 8) ? sh[lane] : 0.f;
    #pragma unroll
    for (int o = 4; o > 0; o >>= 1) r += __shfl_xor_sync(0xffffffffu, r, o);
    r = __shfl_sync(0xffffffffu, r, 0);
    __syncthreads();
    return r;
}

// ---------------- embedding --------------------------------------------------
__global__ __launch_bounds__(256) void embed_kernel(
    const int* __restrict__ idx, const float* __restrict__ tok_w,
    const float* __restrict__ pos, float* __restrict__ x)
{
    int i = blockIdx.x * 256 + threadIdx.x;          // over B*T*E/4 float4s
    const int E4 = Eq / 4;
    int e4 = i % E4;
    int bt = i / E4;
    int t  = bt % Tq;
    int tok = idx[bt];
    float4 tw = ((const float4*)tok_w)[(int64_t)tok * E4 + e4];
    float4 pe = ((const float4*)pos)[(int64_t)t * E4 + e4];
    ((float4*)x)[i] = make_float4(tw.x + pe.x, tw.y + pe.y, tw.z + pe.z, tw.w + pe.w);
}

// ---------------- layernorm (one block per row of E=1024) -------------------
__global__ __launch_bounds__(256) void ln_kernel(
    const float* __restrict__ x, float* __restrict__ y,
    const float* __restrict__ s, const float* __restrict__ b)
{
    int row = blockIdx.x;
    int tid = threadIdx.x;
    const float4* xr = (const float4*)(x + (int64_t)row * Eq);
    float4 v = xr[tid];
    float tot = block_reduce_sum(v.x + v.y + v.z + v.w);
    float mean = tot * (1.f / Eq);
    float dx = v.x - mean, dy = v.y - mean, dz = v.z - mean, dw = v.w - mean;
    float tot2 = block_reduce_sum(dx*dx + dy*dy + dz*dz + dw*dw);
    float inv = rsqrtf(tot2 * (1.f / Eq) + 1e-5f);
    float4 sv = ((const float4*)s)[tid];
    float4 bv = ((const float4*)b)[tid];
    float4 o;
    o.x = dx * inv * sv.x + bv.x;
    o.y = dy * inv * sv.y + bv.y;
    o.z = dz * inv * sv.z + bv.z;
    o.w = dw * inv * sv.w + bv.w;
    ((float4*)(y + (int64_t)row * Eq))[tid] = o;
}

// ---------------- tf32 helpers -----------------------------------------------
__device__ __forceinline__ uint32_t f2tf(float f) {
    uint32_t u;
    asm("cvt.rna.tf32.f32 %0, %1;" : "=r"(u) : "f"(f));
    return u;
}

#define MMA_TF32(c, a, b)                                                     \
    asm volatile(                                                             \
        "mma.sync.aligned.m16n8k8.row.col.f32.tf32.tf32.f32 "                 \
        "{%0,%1,%2,%3}, {%4,%5,%6,%7}, {%8,%9}, {%0,%1,%2,%3};"               \
        : "+f"(c[0]), "+f"(c[1]), "+f"(c[2]), "+f"(c[3])                      \
        : "r"(a[0]), "r"(a[1]), "r"(a[2]), "r"(a[3]), "r"(b[0]), "r"(b[1]))

#define MMA_TF32_V(c, av, bv)                                                 \
    asm volatile(                                                             \
        "mma.sync.aligned.m16n8k8.row.col.f32.tf32.tf32.f32 "                 \
        "{%0,%1,%2,%3}, {%4,%5,%6,%7}, {%8,%9}, {%0,%1,%2,%3};"               \
        : "+f"(c[0]), "+f"(c[1]), "+f"(c[2]), "+f"(c[3])                      \
        : "r"(av.x), "r"(av.y), "r"(av.z), "r"(av.w), "r"(bv.x), "r"(bv.y))

// ---------------- flash attention (causal, D=64) -----------------------------
// One block = one (b, h, 128-row q tile). 256 threads = 8 warps, each warp
// owns a 16-row slab. S kept in registers; online softmax; P staged via smem
// as tf32; O accumulated in fp32 registers. Never materializes T x T.
#define FL_SMEM_WORDS (8448 + 8448 + 8704 + 16896)

__global__ void __launch_bounds__(256, 1) flash_kernel(
    const float* __restrict__ q, const float* __restrict__ k,
    const float* __restrict__ v, float* __restrict__ o)
{
    extern __shared__ uint32_t dsm[];
    uint32_t* Qs = dsm;             // [64][132]
    uint32_t* Ks = Qs + 8448;       // [64][132]
    uint32_t* Vs = Ks + 8448;       // [128][68]
    uint32_t* Ps = Vs + 8704;       // [128][132]

    int bh = blockIdx.y;
    int b  = bh >> 4, hh = bh & 15;
    int qi = (int)gridDim.x - 1 - blockIdx.x;   // heavy tiles first
    int q0 = qi * 128;

    const float* qbase = q + (int64_t)b * Tq * Eq + hh * Dq;
    const float* kbase = k + (int64_t)b * Tq * Eq + hh * Dq;
    const float* vbase = v + (int64_t)b * Tq * Eq + hh * Dq;
    float*       obase = o + (int64_t)b * Tq * Eq + hh * Dq;

    int tid = threadIdx.x, warp = tid >> 5, lane = tid & 31;
    int g = lane >> 2, t = lane & 3;
    int m0 = warp * 16;

    // ---- load Q tile (once) ----
    {
        int mrow = tid >> 4;
        int d4   = (tid & 15) * 4;
        #pragma unroll
        for (int it = 0; it < 8; it++) {
            int m = mrow + it * 16;
            float4 qv = *(const float4*)(qbase + (int64_t)(q0 + m) * Eq + d4);
            Qs[(d4 + 0) * 132 + m] = f2tf(qv.x);
            Qs[(d4 + 1) * 132 + m] = f2tf(qv.y);
            Qs[(d4 + 2) * 132 + m] = f2tf(qv.z);
            Qs[(d4 + 3) * 132 + m] = f2tf(qv.w);
        }
    }

    float m_run0 = -1e30f, m_run1 = -1e30f;
    float l_run0 = 0.f,    l_run1 = 0.f;
    float oacc[8][4];
    #pragma unroll
    for (int nj = 0; nj < 8; nj++)
        #pragma unroll
        for (int e = 0; e < 4; e++) oacc[nj][e] = 0.f;

    int r0 = q0 + m0 + g, r1 = r0 + 8;

    for (int jt = 0; jt <= qi; jt++) {
        int kv0 = jt * 128;
        __syncthreads();
        // ---- load K, V tiles ----
        {
            int nrow = tid >> 4;
            int d4   = (tid & 15) * 4;
            #pragma unroll
            for (int it = 0; it < 8; it++) {
                int n = nrow + it * 16;
                float4 kv_ = *(const float4*)(kbase + (int64_t)(kv0 + n) * Eq + d4);
                Ks[(d4 + 0) * 132 + n] = f2tf(kv_.x);
                Ks[(d4 + 1) * 132 + n] = f2tf(kv_.y);
                Ks[(d4 + 2) * 132 + n] = f2tf(kv_.z);
                Ks[(d4 + 3) * 132 + n] = f2tf(kv_.w);
                float4 vv = *(const float4*)(vbase + (int64_t)(kv0 + n) * Eq + d4);
                Vs[n * 68 + d4 + 0] = f2tf(vv.x);
                Vs[n * 68 + d4 + 1] = f2tf(vv.y);
                Vs[n * 68 + d4 + 2] = f2tf(vv.z);
                Vs[n * 68 + d4 + 3] = f2tf(vv.w);
            }
        }
        __syncthreads();

        // ---- S = Q @ K^T for this warp's 16-row slab (16 x 128) ----
        float sacc[16][4];
        #pragma unroll
        for (int j = 0; j < 16; j++)
            #pragma unroll
            for (int e = 0; e < 4; e++) sacc[j][e] = 0.f;

        #pragma unroll
        for (int kb = 0; kb < 8; kb++) {
            uint32_t af[4];
            af[0] = Qs[(kb * 8 + t    ) * 132 + m0 + g];
            af[1] = Qs[(kb * 8 + t    ) * 132 + m0 + g + 8];
            af[2] = Qs[(kb * 8 + t + 4) * 132 + m0 + g];
            af[3] = Qs[(kb * 8 + t + 4) * 132 + m0 + g + 8];
            #pragma unroll
            for (int j = 0; j < 16; j++) {
                uint32_t bf[2];
                bf[0] = Ks[(kb * 8 + t    ) * 132 + j * 8 + g];
                bf[1] = Ks[(kb * 8 + t + 4) * 132 + j * 8 + g];
                MMA_TF32(sacc[j], af, bf);
            }
        }

        // ---- scale + causal mask + row max ----
        float mx0 = -1e30f, mx1 = -1e30f;
        #pragma unroll
        for (int j = 0; j < 16; j++) {
            #pragma unroll
            for (int e = 0; e < 2; e++) {
                int c = kv0 + j * 8 + t * 2 + e;
                float s0 = sacc[j][e]     * 0.125f;
                float s1 = sacc[j][e + 2] * 0.125f;
                if (c > r0) s0 = -1e30f;
                if (c > r1) s1 = -1e30f;
                sacc[j][e]     = s0;
                sacc[j][e + 2] = s1;
                mx0 = fmaxf(mx0, s0);
                mx1 = fmaxf(mx1, s1);
            }
        }
        mx0 = fmaxf(mx0, __shfl_xor_sync(0xffffffffu, mx0, 1));
        mx0 = fmaxf(mx0, __shfl_xor_sync(0xffffffffu, mx0, 2));
        mx1 = fmaxf(mx1, __shfl_xor_sync(0xffffffffu, mx1, 1));
        mx1 = fmaxf(mx1, __shfl_xor_sync(0xffffffffu, mx1, 2));

        float mnew0 = fmaxf(m_run0, mx0);
        float mnew1 = fmaxf(m_run1, mx1);
        float f0 = __expf(m_run0 - mnew0);
        float f1 = __expf(m_run1 - mnew1);

        // ---- P = exp(S - m), write to smem (tf32), row sums ----
        float sum0 = 0.f, sum1 = 0.f;
        #pragma unroll
        for (int j = 0; j < 16; j++) {
            #pragma unroll
            for (int e = 0; e < 2; e++) {
                float p0 = __expf(sacc[j][e]     - mnew0);
                float p1 = __expf(sacc[j][e + 2] - mnew1);
                sum0 += p0;
                sum1 += p1;
                int krow = j * 8 + t * 2 + e;
                Ps[krow * 132 + m0 + g]     = f2tf(p0);
                Ps[krow * 132 + m0 + g + 8] = f2tf(p1);
            }
        }
        sum0 += __shfl_xor_sync(0xffffffffu, sum0, 1);
        sum0 += __shfl_xor_sync(0xffffffffu, sum0, 2);
        sum1 += __shfl_xor_sync(0xffffffffu, sum1, 1);
        sum1 += __shfl_xor_sync(0xffffffffu, sum1, 2);

        l_run0 = l_run0 * f0 + sum0;
        l_run1 = l_run1 * f1 + sum1;
        m_run0 = mnew0;
        m_run1 = mnew1;

        // ---- rescale O accumulator ----
        #pragma unroll
        for (int nj = 0; nj < 8; nj++) {
            oacc[nj][0] *= f0; oacc[nj][1] *= f0;
            oacc[nj][2] *= f1; oacc[nj][3] *= f1;
        }
        __syncwarp();

        // ---- O += P @ V  (K-dim = 128) ----
        #pragma unroll
        for (int kb = 0; kb < 16; kb++) {
            uint32_t af[4];
            af[0] = Ps[(kb * 8 + t    ) * 132 + m0 + g];
            af[1] = Ps[(kb * 8 + t    ) * 132 + m0 + g + 8];
            af[2] = Ps[(kb * 8 + t + 4) * 132 + m0 + g];
            af[3] = Ps[(kb * 8 + t + 4) * 132 + m0 + g + 8];
            #pragma unroll
            for (int nj = 0; nj < 8; nj++) {
                uint32_t bf[2];
                bf[0] = Vs[(kb * 8 + t    ) * 68 + nj * 8 + g];
                bf[1] = Vs[(kb * 8 + t + 4) * 68 + nj * 8 + g];
                MMA_TF32(oacc[nj], af, bf);
            }
        }
    }

    // ---- epilogue: normalize and store ----
    float inv0 = 1.f / l_run0;
    float inv1 = 1.f / l_run1;
    #pragma unroll
    for (int nj = 0; nj < 8; nj++) {
        int c = nj * 8 + t * 2;
        *(float2*)(obase + (int64_t)r0 * Eq + c) =
            make_float2(oacc[nj][0] * inv0, oacc[nj][1] * inv0);
        *(float2*)(obase + (int64_t)r1 * Eq + c) =
            make_float2(oacc[nj][2] * inv1, oacc[nj][3] * inv1);
    }
}

// ---------------- TF32 tensor-core GEMM (fragment smem, conflict-free) -------
// C = alpha * A @ B (+bias[n]) (+resid) (ReLU optional)
// A: M x K row-major (lda). B: K x N row-major (ldb).
// Block tile BM x 128 x 16, 8 warps (BM/2 x 32 warp tiles).
// Smem holds m16n8k8 fragments directly:
//   Af[buf][mtile][kb][lane][4]  -> one LDS.128 = full A fragment
//   Bf[buf][ntile][kb][lane][2]  -> one LDS.64  = full B fragment
// Each thread OWNS whole (fragment, lane) cells:
//   A cell: rows mt*16+(l>>2), +8; cols kb*8+(l&3), +4  -> 4x LDG.32, 1x STS.128
//   B cell: col  nt*8+(l>>2);  rows kb*8+(l&3), +4      -> 2x LDG.32, 1x STS.64
// Within a warp the fragment id is constant and l = lane -> STS pattern is
// const + lane*4 (A) / const + lane*2 (B) words: conflict-free.
// All shapes are exact tile multiples (asserted by call sites) -> no bounds.
template<int BM>
__global__ __launch_bounds__(256, 2) void gemm_tc(
    const float* __restrict__ A, const float* __restrict__ Bm, float* __restrict__ C,
    int M, int N, int K, int lda, int ldb, int ldc,
    const float* __restrict__ bias, const float* __restrict__ resid,
    int relu, float alpha,
    const float* B1, float* C1, const float* B2, float* C2)
{
    constexpr int MT = BM / 16;        // m-tiles per block
    constexpr int II = BM / 32;        // i-tiles per warp
    constexpr int AP = BM / 64;        // A cells per thread
    __shared__ __align__(16) uint32_t Af[2][MT][2][32][4];
    __shared__ __align__(16) uint32_t Bf[2][16][2][32][2];

    int zo = blockIdx.z;
    if (B1 && zo == 1) { Bm = B1; C = C1; }
    if (B2 && zo == 2) { Bm = B2; C = C2; }

    int row0 = blockIdx.y * BM;
    int col0 = blockIdx.x * 128;

    int tid  = threadIdx.x;
    int warp = tid >> 5, lane = tid & 31;
    int g = lane >> 2, t = lane & 3;
    int wMt = (warp & 1) * (MT / 2);   // warp m-tile offset
    int wNt = (warp >> 1) * 4;         // warp n-tile offset (32 cols)
    int wM = wMt * 16;
    int wN = wNt * 8;

    float acc[II][4][4];
    #pragma unroll
    for (int i = 0; i < II; i++)
        #pragma unroll
        for (int j = 0; j < 4; j++)
            #pragma unroll
            for (int e = 0; e < 4; e++) acc[i][j][e] = 0.f;

    float a_st[AP][4];
    float b_st[4][2];

    auto loadg = [&](int k0) {
        #pragma unroll
        for (int p = 0; p < AP; p++) {
            int idx = tid + p * 256;
            int f = idx >> 5, l = idx & 31;
            int mt = f >> 1, kb = f & 1;
            const float* ap = A + (int64_t)(row0 + mt * 16 + (l >> 2)) * lda
                                + k0 + kb * 8 + (l & 3);
            a_st[p][0] = ap[0];
            a_st[p][1] = ap[(int64_t)8 * lda];
            a_st[p][2] = ap[4];
            a_st[p][3] = ap[(int64_t)8 * lda + 4];
        }
        #pragma unroll
        for (int p = 0; p < 4; p++) {
            int idx = tid + p * 256;
            int f = idx >> 5, l = idx & 31;
            int nt = f >> 1, kb = f & 1;
            const float* bp = Bm + (int64_t)(k0 + kb * 8 + (l & 3)) * ldb
                                 + col0 + nt * 8 + (l >> 2);
            b_st[p][0] = bp[0];
            b_st[p][1] = bp[(int64_t)4 * ldb];
        }
    };

    auto stores = [&](int buf) {
        #pragma unroll
        for (int p = 0; p < AP; p++) {
            int idx = tid + p * 256;
            int f = idx >> 5, l = idx & 31;
            int mt = f >> 1, kb = f & 1;
            uint4 w = make_uint4(f2tf(a_st[p][0]), f2tf(a_st[p][1]),
                                 f2tf(a_st[p][2]), f2tf(a_st[p][3]));
            *(uint4*)&Af[buf][mt][kb][l][0] = w;
        }
        #pragma unroll
        for (int p = 0; p < 4; p++) {
            int idx = tid + p * 256;
            int f = idx >> 5, l = idx & 31;
            int nt = f >> 1, kb = f & 1;
            uint2 w = make_uint2(f2tf(b_st[p][0]), f2tf(b_st[p][1]));
            *(uint2*)&Bf[buf][nt][kb][l][0] = w;
        }
    };

    auto compute = [&](int buf) {
        #pragma unroll
        for (int ks = 0; ks < 2; ks++) {
            uint4 av[II];
            uint2 bv[4];
            #pragma unroll
            for (int i = 0; i < II; i++)
                av[i] = *(const uint4*)&Af[buf][wMt + i][ks][lane][0];
            #pragma unroll
            for (int j = 0; j < 4; j++)
                bv[j] = *(const uint2*)&Bf[buf][wNt + j][ks][lane][0];
            #pragma unroll
            for (int i = 0; i < II; i++)
                #pragma unroll
                for (int j = 0; j < 4; j++)
                    MMA_TF32_V(acc[i][j], av[i], bv[j]);
        }
    };

    // pipeline: prologue
    loadg(0);
    stores(0);
    __syncthreads();

    int nit = K >> 4;
    int buf = 0;
    for (int itk = 1; itk < nit; itk++) {
        loadg(itk << 4);
        compute(buf);
        stores(buf ^ 1);
        __syncthreads();
        buf ^= 1;
    }
    compute(buf);

    // ---- epilogue ----
    #pragma unroll
    for (int i = 0; i < II; i++) {
        int r0 = row0 + wM + i * 16 + g;
        #pragma unroll
        for (int j = 0; j < 4; j++) {
            int c = col0 + wN + j * 8 + t * 2;
            #pragma unroll
            for (int half = 0; half < 2; half++) {
                int r = r0 + half * 8;
                float v0 = alpha * acc[i][j][half * 2 + 0];
                float v1 = alpha * acc[i][j][half * 2 + 1];
                if (bias) { v0 += bias[c]; v1 += bias[c + 1]; }
                if (resid) {
                    float2 rv = *(const float2*)(resid + (int64_t)r * ldc + c);
                    v0 += rv.x; v1 += rv.y;
                }
                if (relu) { v0 = fmaxf(v0, 0.f); v1 = fmaxf(v1, 0.f); }
                *(float2*)(C + (int64_t)r * ldc + c) = make_float2(v0, v1);
            }
        }
    }
}

// ---------------- host orchestration ----------------------------------------
static inline dim3 ggrid(int M, int N, int batch, int bm) {
    return dim3((unsigned)((N + 127) / 128), (unsigned)((M + bm - 1) / bm), (unsigned)batch);
}

extern "C" void kernel_launch(void* const* d_in, const int* in_sizes, int n_in,
                              void* d_out, int out_size)
{
    const int*   idx    = (const int*)  d_in[0];
    const float* tok_w  = (const float*)d_in[1];
    const float* pos    = (const float*)d_in[2];
    const float* ln1_s  = (const float*)d_in[3];
    const float* ln1_b  = (const float*)d_in[4];
    const float* wq     = (const float*)d_in[5];
    const float* wk     = (const float*)d_in[6];
    const float* wv     = (const float*)d_in[7];
    const float* wo     = (const float*)d_in[8];
    const float* bo     = (const float*)d_in[9];
    const float* ln2_s  = (const float*)d_in[10];
    const float* ln2_b  = (const float*)d_in[11];
    const float* w1     = (const float*)d_in[12];
    const float* b1     = (const float*)d_in[13];
    const float* w2     = (const float*)d_in[14];
    const float* b2     = (const float*)d_in[15];
    const float* lnf_s  = (const float*)d_in[16];
    const float* lnf_b  = (const float*)d_in[17];
    const float* head_w = (const float*)d_in[18];
    const float* head_b = (const float*)d_in[19];
    float* out = (float*)d_out;

    float *x, *h, *q, *k, *v, *o, *ff;
    cudaGetSymbolAddress((void**)&x,   g_x);
    cudaGetSymbolAddress((void**)&h,   g_h);
    cudaGetSymbolAddress((void**)&q,   g_q);
    cudaGetSymbolAddress((void**)&k,   g_k);
    cudaGetSymbolAddress((void**)&v,   g_v);
    cudaGetSymbolAddress((void**)&o,   g_o);
    cudaGetSymbolAddress((void**)&ff,  g_ff);

    const int M = Bq * Tq;                  // 2048
    const int flashSmem = FL_SMEM_WORDS * 4;
    cudaFuncSetAttribute(flash_kernel,
        cudaFuncAttributeMaxDynamicSharedMemorySize, flashSmem);

    // embedding
    embed_kernel<<<(M * Eq / 4 + 255) / 256, 256>>>(idx, tok_w, pos, x);

    for (int l = 0; l < Lq; l++) {
        const float* Wq = wq + (int64_t)l * Eq * Eq;
        const float* Wk = wk + (int64_t)l * Eq * Eq;
        const float* Wv = wv + (int64_t)l * Eq * Eq;
        const float* Wo = wo + (int64_t)l * Eq * Eq;
        const float* W1 = w1 + (int64_t)l * Eq * FFq;
        const float* W2 = w2 + (int64_t)l * FFq * Eq;

        // ln1
        ln_kernel<<<M, 256>>>(x, h, ln1_s + l * Eq, ln1_b + l * Eq);

        // fused q/k/v projections (z selects weight + output)
        gemm_tc<128><<<ggrid(M, Eq, 3, 128), 256>>>(h, Wq, q,
            M, Eq, Eq, Eq, Eq, Eq,
            nullptr, nullptr, 0, 1.0f,
            Wk, k, Wv, v);

        // fused flash attention: o = softmax(causal(qk^T/sqrt(d))) @ v
        flash_kernel<<<dim3(Tq / 128, Bq * Hq), 256, flashSmem>>>(q, k, v, o);

        // x = x + o @ Wo + bo
        gemm_tc<64><<<ggrid(M, Eq, 1, 64), 256>>>(o, Wo, x,
            M, Eq, Eq, Eq, Eq, Eq,
            bo + l * Eq, x, 0, 1.0f,
            nullptr, nullptr, nullptr, nullptr);

        // ln2
        ln_kernel<<<M, 256>>>(x, h, ln2_s + l * Eq, ln2_b + l * Eq);

        // ff = relu(h @ W1 + b1)
        gemm_tc<128><<<ggrid(M, FFq, 1, 128), 256>>>(h, W1, ff,
            M, FFq, Eq, Eq, FFq, FFq,
            b1 + l * FFq, nullptr, 1, 1.0f,
            nullptr, nullptr, nullptr, nullptr);

        // x = x + ff @ W2 + b2
        gemm_tc<64><<<ggrid(M, Eq, 1, 64), 256>>>(ff, W2, x,
            M, Eq, FFq, FFq, Eq, Eq,
            b2 + l * Eq, x, 0, 1.0f,
            nullptr, nullptr, nullptr, nullptr);
    }

    // final layernorm
    ln_kernel<<<M, 256>>>(x, h, lnf_s, lnf_b);

    // logits = h @ head_w + head_b
    gemm_tc<128><<<ggrid(M, Vq, 1, 128), 256>>>(h, head_w, out,
        M, Vq, Eq, Eq, Vq, Vq,
        head_b, nullptr, 0, 1.0f,
        nullptr, nullptr, nullptr, nullptr);
}

// round 7
// speedup vs baseline: 2.9891x; 1.2845x over previous
#include <cuda_runtime.h>
#include <cstdint>

#define Bq 2
#define Tq 1024
#define Eq 1024
#define Hq 16
#define Dq 64
#define Lq 6
#define FFq 4096
#define Vq 32000

// ---------------- scratch (device globals; no runtime allocation) ----------
__device__ float    g_x [Bq*Tq*Eq];
__device__ uint32_t g_h [Bq*Tq*Eq];
__device__ uint32_t g_q [Bq*Tq*Eq];
__device__ uint32_t g_k [Bq*Tq*Eq];
__device__ uint32_t g_v [Bq*Tq*Eq];
__device__ uint32_t g_o [Bq*Tq*Eq];
__device__ uint32_t g_ff[Bq*Tq*FFq];
// tf32 weight copies
__device__ uint32_t g_wq[Lq*Eq*Eq];
__device__ uint32_t g_wk[Lq*Eq*Eq];
__device__ uint32_t g_wv[Lq*Eq*Eq];
__device__ uint32_t g_wo[Lq*Eq*Eq];
__device__ uint32_t g_w1[Lq*Eq*FFq];
__device__ uint32_t g_w2[Lq*FFq*Eq];
__device__ uint32_t g_hw[Eq*Vq];

// ---------------- tf32 helpers -----------------------------------------------
__device__ __forceinline__ uint32_t f2tf(float f) {
    uint32_t u;
    asm("cvt.rna.tf32.f32 %0, %1;" : "=r"(u) : "f"(f));
    return u;
}

#define MMA_TF32(c, a, b)                                                     \
    asm volatile(                                                             \
        "mma.sync.aligned.m16n8k8.row.col.f32.tf32.tf32.f32 "                 \
        "{%0,%1,%2,%3}, {%4,%5,%6,%7}, {%8,%9}, {%0,%1,%2,%3};"               \
        : "+f"(c[0]), "+f"(c[1]), "+f"(c[2]), "+f"(c[3])                      \
        : "r"(a[0]), "r"(a[1]), "r"(a[2]), "r"(a[3]), "r"(b[0]), "r"(b[1]))

__device__ __forceinline__ void cp16(uint32_t* dst, const uint32_t* src) {
    uint32_t d = (uint32_t)__cvta_generic_to_shared(dst);
    asm volatile("cp.async.cg.shared.global [%0], [%1], 16;\n" :: "r"(d), "l"(src));
}
#define CP_COMMIT() asm volatile("cp.async.commit_group;\n" ::)
#define CP_WAIT2()  asm volatile("cp.async.wait_group 2;\n" ::)

// ---------------- weight convert (fp32 -> tf32 bits) -------------------------
__global__ __launch_bounds__(256) void cvt_kernel(
    const float* __restrict__ src, uint32_t* __restrict__ dst, int n4)
{
    int i = blockIdx.x * 256 + threadIdx.x;
    if (i >= n4) return;
    float4 v = ((const float4*)src)[i];
    ((uint4*)dst)[i] = make_uint4(f2tf(v.x), f2tf(v.y), f2tf(v.z), f2tf(v.w));
}

// ---------------- block reduction (256 threads) ------------------------------
__device__ __forceinline__ float block_reduce_sum(float v) {
    __shared__ float sh[8];
    #pragma unroll
    for (int o = 16; o > 0; o >>= 1) v += __shfl_xor_sync(0xffffffffu, v, o);
    int lane = threadIdx.x & 31, w = threadIdx.x >> 5;
    if (lane == 0) sh[w] = v;
    __syncthreads();
    float r = (lane < 8) ? sh[lane] : 0.f;
    #pragma unroll
    for (int o = 4; o > 0; o >>= 1) r += __shfl_xor_sync(0xffffffffu, r, o);
    r = __shfl_sync(0xffffffffu, r, 0);
    __syncthreads();
    return r;
}

// ---------------- embedding --------------------------------------------------
__global__ __launch_bounds__(256) void embed_kernel(
    const int* __restrict__ idx, const float* __restrict__ tok_w,
    const float* __restrict__ pos, float* __restrict__ x)
{
    int i = blockIdx.x * 256 + threadIdx.x;
    const int E4 = Eq / 4;
    int e4 = i % E4;
    int bt = i / E4;
    int t  = bt % Tq;
    int tok = idx[bt];
    float4 tw = ((const float4*)tok_w)[(int64_t)tok * E4 + e4];
    float4 pe = ((const float4*)pos)[(int64_t)t * E4 + e4];
    ((float4*)x)[i] = make_float4(tw.x + pe.x, tw.y + pe.y, tw.z + pe.z, tw.w + pe.w);
}

// ---------------- layernorm: fp32 in, tf32 bits out --------------------------
__global__ __launch_bounds__(256) void ln_kernel(
    const float* __restrict__ x, uint32_t* __restrict__ y,
    const float* __restrict__ s, const float* __restrict__ b)
{
    int row = blockIdx.x;
    int tid = threadIdx.x;
    float4 v = ((const float4*)(x + (int64_t)row * Eq))[tid];
    float tot = block_reduce_sum(v.x + v.y + v.z + v.w);
    float mean = tot * (1.f / Eq);
    float dx = v.x - mean, dy = v.y - mean, dz = v.z - mean, dw = v.w - mean;
    float tot2 = block_reduce_sum(dx*dx + dy*dy + dz*dz + dw*dw);
    float inv = rsqrtf(tot2 * (1.f / Eq) + 1e-5f);
    float4 sv = ((const float4*)s)[tid];
    float4 bv = ((const float4*)b)[tid];
    uint4 o;
    o.x = f2tf(dx * inv * sv.x + bv.x);
    o.y = f2tf(dy * inv * sv.y + bv.y);
    o.z = f2tf(dz * inv * sv.z + bv.z);
    o.w = f2tf(dw * inv * sv.w + bv.w);
    ((uint4*)(y + (int64_t)row * Eq))[tid] = o;
}

// ---------------- flash attention (causal, D=64, tf32 in/out) ----------------
#define FL_SMEM_WORDS (8448 + 8448 + 8704 + 16896)

__global__ void __launch_bounds__(256, 1) flash_kernel(
    const uint32_t* __restrict__ q, const uint32_t* __restrict__ k,
    const uint32_t* __restrict__ v, uint32_t* __restrict__ o)
{
    extern __shared__ uint32_t dsm[];
    uint32_t* Qs = dsm;             // [64][132]
    uint32_t* Ks = Qs + 8448;       // [64][132]
    uint32_t* Vs = Ks + 8448;       // [128][68]
    uint32_t* Ps = Vs + 8704;       // [128][132]

    int bh = blockIdx.y;
    int b  = bh >> 4, hh = bh & 15;
    int qi = (int)gridDim.x - 1 - blockIdx.x;   // heavy tiles first
    int q0 = qi * 128;

    const uint32_t* qbase = q + (int64_t)b * Tq * Eq + hh * Dq;
    const uint32_t* kbase = k + (int64_t)b * Tq * Eq + hh * Dq;
    const uint32_t* vbase = v + (int64_t)b * Tq * Eq + hh * Dq;
    uint32_t*       obase = o + (int64_t)b * Tq * Eq + hh * Dq;

    int tid = threadIdx.x, warp = tid >> 5, lane = tid & 31;
    int g = lane >> 2, t = lane & 3;
    int m0 = warp * 16;

    // ---- load Q tile (once) ----
    {
        int mrow = tid >> 4;
        int d4   = (tid & 15) * 4;
        #pragma unroll
        for (int it = 0; it < 8; it++) {
            int m = mrow + it * 16;
            uint4 qv = *(const uint4*)(qbase + (int64_t)(q0 + m) * Eq + d4);
            Qs[(d4 + 0) * 132 + m] = qv.x;
            Qs[(d4 + 1) * 132 + m] = qv.y;
            Qs[(d4 + 2) * 132 + m] = qv.z;
            Qs[(d4 + 3) * 132 + m] = qv.w;
        }
    }

    float m_run0 = -1e30f, m_run1 = -1e30f;
    float l_run0 = 0.f,    l_run1 = 0.f;
    float oacc[8][4];
    #pragma unroll
    for (int nj = 0; nj < 8; nj++)
        #pragma unroll
        for (int e = 0; e < 4; e++) oacc[nj][e] = 0.f;

    int r0 = q0 + m0 + g, r1 = r0 + 8;

    for (int jt = 0; jt <= qi; jt++) {
        int kv0 = jt * 128;
        __syncthreads();
        {
            int nrow = tid >> 4;
            int d4   = (tid & 15) * 4;
            #pragma unroll
            for (int it = 0; it < 8; it++) {
                int n = nrow + it * 16;
                uint4 kv_ = *(const uint4*)(kbase + (int64_t)(kv0 + n) * Eq + d4);
                Ks[(d4 + 0) * 132 + n] = kv_.x;
                Ks[(d4 + 1) * 132 + n] = kv_.y;
                Ks[(d4 + 2) * 132 + n] = kv_.z;
                Ks[(d4 + 3) * 132 + n] = kv_.w;
                uint4 vv = *(const uint4*)(vbase + (int64_t)(kv0 + n) * Eq + d4);
                *(uint4*)&Vs[n * 68 + d4] = vv;
            }
        }
        __syncthreads();

        float sacc[16][4];
        #pragma unroll
        for (int j = 0; j < 16; j++)
            #pragma unroll
            for (int e = 0; e < 4; e++) sacc[j][e] = 0.f;

        #pragma unroll
        for (int kb = 0; kb < 8; kb++) {
            uint32_t af[4];
            af[0] = Qs[(kb * 8 + t    ) * 132 + m0 + g];
            af[1] = Qs[(kb * 8 + t    ) * 132 + m0 + g + 8];
            af[2] = Qs[(kb * 8 + t + 4) * 132 + m0 + g];
            af[3] = Qs[(kb * 8 + t + 4) * 132 + m0 + g + 8];
            #pragma unroll
            for (int j = 0; j < 16; j++) {
                uint32_t bf[2];
                bf[0] = Ks[(kb * 8 + t    ) * 132 + j * 8 + g];
                bf[1] = Ks[(kb * 8 + t + 4) * 132 + j * 8 + g];
                MMA_TF32(sacc[j], af, bf);
            }
        }

        float mx0 = -1e30f, mx1 = -1e30f;
        #pragma unroll
        for (int j = 0; j < 16; j++) {
            #pragma unroll
            for (int e = 0; e < 2; e++) {
                int c = kv0 + j * 8 + t * 2 + e;
                float s0 = sacc[j][e]     * 0.125f;
                float s1 = sacc[j][e + 2] * 0.125f;
                if (c > r0) s0 = -1e30f;
                if (c > r1) s1 = -1e30f;
                sacc[j][e]     = s0;
                sacc[j][e + 2] = s1;
                mx0 = fmaxf(mx0, s0);
                mx1 = fmaxf(mx1, s1);
            }
        }
        mx0 = fmaxf(mx0, __shfl_xor_sync(0xffffffffu, mx0, 1));
        mx0 = fmaxf(mx0, __shfl_xor_sync(0xffffffffu, mx0, 2));
        mx1 = fmaxf(mx1, __shfl_xor_sync(0xffffffffu, mx1, 1));
        mx1 = fmaxf(mx1, __shfl_xor_sync(0xffffffffu, mx1, 2));

        float mnew0 = fmaxf(m_run0, mx0);
        float mnew1 = fmaxf(m_run1, mx1);
        float f0 = __expf(m_run0 - mnew0);
        float f1 = __expf(m_run1 - mnew1);

        float sum0 = 0.f, sum1 = 0.f;
        #pragma unroll
        for (int j = 0; j < 16; j++) {
            #pragma unroll
            for (int e = 0; e < 2; e++) {
                float p0 = __expf(sacc[j][e]     - mnew0);
                float p1 = __expf(sacc[j][e + 2] - mnew1);
                sum0 += p0;
                sum1 += p1;
                int krow = j * 8 + t * 2 + e;
                Ps[krow * 132 + m0 + g]     = f2tf(p0);
                Ps[krow * 132 + m0 + g + 8] = f2tf(p1);
            }
        }
        sum0 += __shfl_xor_sync(0xffffffffu, sum0, 1);
        sum0 += __shfl_xor_sync(0xffffffffu, sum0, 2);
        sum1 += __shfl_xor_sync(0xffffffffu, sum1, 1);
        sum1 += __shfl_xor_sync(0xffffffffu, sum1, 2);

        l_run0 = l_run0 * f0 + sum0;
        l_run1 = l_run1 * f1 + sum1;
        m_run0 = mnew0;
        m_run1 = mnew1;

        #pragma unroll
        for (int nj = 0; nj < 8; nj++) {
            oacc[nj][0] *= f0; oacc[nj][1] *= f0;
            oacc[nj][2] *= f1; oacc[nj][3] *= f1;
        }
        __syncwarp();

        #pragma unroll
        for (int kb = 0; kb < 16; kb++) {
            uint32_t af[4];
            af[0] = Ps[(kb * 8 + t    ) * 132 + m0 + g];
            af[1] = Ps[(kb * 8 + t    ) * 132 + m0 + g + 8];
            af[2] = Ps[(kb * 8 + t + 4) * 132 + m0 + g];
            af[3] = Ps[(kb * 8 + t + 4) * 132 + m0 + g + 8];
            #pragma unroll
            for (int nj = 0; nj < 8; nj++) {
                uint32_t bf[2];
                bf[0] = Vs[(kb * 8 + t    ) * 68 + nj * 8 + g];
                bf[1] = Vs[(kb * 8 + t + 4) * 68 + nj * 8 + g];
                MMA_TF32(oacc[nj], af, bf);
            }
        }
    }

    // ---- epilogue: normalize and store as tf32 bits ----
    float inv0 = 1.f / l_run0;
    float inv1 = 1.f / l_run1;
    #pragma unroll
    for (int nj = 0; nj < 8; nj++) {
        int c = nj * 8 + t * 2;
        *(uint2*)(obase + (int64_t)r0 * Eq + c) =
            make_uint2(f2tf(oacc[nj][0] * inv0), f2tf(oacc[nj][1] * inv0));
        *(uint2*)(obase + (int64_t)r1 * Eq + c) =
            make_uint2(f2tf(oacc[nj][2] * inv1), f2tf(oacc[nj][3] * inv1));
    }
}

// ---------------- TF32 GEMM: cp.async 4-stage pipeline -----------------------
// A, B already tf32 bits. A: M x K row-major. B: K x N row-major.
// Block tile BM x 128 x 16, 8 warps ((BM/2) x 32 warp tiles).
// Smem per stage: As[BM][20] (m-major, stride-20 pad -> conflict-free frag LDS),
//                 Bs[16][132].
// All problem shapes are exact tile multiples -> no bounds checks.
// cvt_out: epilogue stores tf32 bits (for q/k/v/ff) instead of fp32.
template<int BM>
__global__ __launch_bounds__(256, 2) void gemm_tc(
    const uint32_t* __restrict__ A, const uint32_t* __restrict__ Bm, float* C,
    int M, int N, int K, int lda, int ldb, int ldc,
    const float* __restrict__ bias, const float* __restrict__ resid,
    int relu, int cvt_out,
    const uint32_t* B1, float* C1, const uint32_t* B2, float* C2)
{
    constexpr int II   = BM / 32;          // i-tiles per warp
    constexpr int ASTG = BM * 20;          // A stage words
    constexpr int BSTG = 16 * 132;         // B stage words
    extern __shared__ uint32_t smem[];
    uint32_t* As = smem;                   // [4][ASTG]
    uint32_t* Bs = smem + 4 * ASTG;        // [4][BSTG]

    int zo = blockIdx.z;
    if (B1 && zo == 1) { Bm = B1; C = C1; }
    if (B2 && zo == 2) { Bm = B2; C = C2; }

    int row0 = blockIdx.y * BM;
    int col0 = blockIdx.x * 128;

    int tid  = threadIdx.x;
    int warp = tid >> 5, lane = tid & 31;
    int g = lane >> 2, t = lane & 3;
    int wM = (warp & 1) * (BM / 2);
    int wN = (warp >> 1) * 32;

    float acc[II][4][4];
    #pragma unroll
    for (int i = 0; i < II; i++)
        #pragma unroll
        for (int j = 0; j < 4; j++)
            #pragma unroll
            for (int e = 0; e < 4; e++) acc[i][j][e] = 0.f;

    auto load_stage = [&](int k0, int stg) {
        uint32_t* as = As + stg * ASTG;
        uint32_t* bs = Bs + stg * BSTG;
        // A: BM rows x 16 words = BM*4 16B-chunks
        #pragma unroll
        for (int p = 0; p < BM / 64; p++) {
            int c = tid + p * 256;
            int row = c >> 2, cc = (c & 3) * 4;
            cp16(as + row * 20 + cc,
                 A + (int64_t)(row0 + row) * lda + k0 + cc);
        }
        // B: 16 rows x 128 words = 512 chunks
        #pragma unroll
        for (int p = 0; p < 2; p++) {
            int c = tid + p * 256;
            int row = c >> 5, cc = (c & 31) * 4;
            cp16(bs + row * 132 + cc,
                 Bm + (int64_t)(k0 + row) * ldb + col0 + cc);
        }
    };

    auto compute = [&](int stg) {
        const uint32_t* as = As + stg * ASTG;
        const uint32_t* bs = Bs + stg * BSTG;
        #pragma unroll
        for (int ks = 0; ks < 2; ks++) {
            int kb = ks * 8;
            uint32_t af[II][4], bf[4][2];
            #pragma unroll
            for (int i = 0; i < II; i++) {
                int m = wM + i * 16 + g;
                af[i][0] = as[(m    ) * 20 + kb + t];
                af[i][1] = as[(m + 8) * 20 + kb + t];
                af[i][2] = as[(m    ) * 20 + kb + t + 4];
                af[i][3] = as[(m + 8) * 20 + kb + t + 4];
            }
            #pragma unroll
            for (int j = 0; j < 4; j++) {
                int n = wN + j * 8 + g;
                bf[j][0] = bs[(kb + t    ) * 132 + n];
                bf[j][1] = bs[(kb + t + 4) * 132 + n];
            }
            #pragma unroll
            for (int i = 0; i < II; i++)
                #pragma unroll
                for (int j = 0; j < 4; j++)
                    MMA_TF32(acc[i][j], af[i], bf[j]);
        }
    };

    int nit = K >> 4;
    // prologue: prefetch 3 stages
    #pragma unroll
    for (int s = 0; s < 3; s++) {
        load_stage(s << 4, s);
        CP_COMMIT();
    }

    for (int itk = 0; itk < nit; itk++) {
        CP_WAIT2();
        __syncthreads();
        if (itk + 3 < nit) load_stage((itk + 3) << 4, (itk + 3) & 3);
        CP_COMMIT();
        compute(itk & 3);
    }

    // ---- epilogue ----
    #pragma unroll
    for (int i = 0; i < II; i++) {
        int r0 = row0 + wM + i * 16 + g;
        #pragma unroll
        for (int j = 0; j < 4; j++) {
            int c = col0 + wN + j * 8 + t * 2;
            #pragma unroll
            for (int half = 0; half < 2; half++) {
                int r = r0 + half * 8;
                float v0 = acc[i][j][half * 2 + 0];
                float v1 = acc[i][j][half * 2 + 1];
                if (bias) { v0 += bias[c]; v1 += bias[c + 1]; }
                if (resid) {
                    float2 rv = *(const float2*)(resid + (int64_t)r * ldc + c);
                    v0 += rv.x; v1 += rv.y;
                }
                if (relu) { v0 = fmaxf(v0, 0.f); v1 = fmaxf(v1, 0.f); }
                if (cvt_out) {
                    *(uint2*)((uint32_t*)C + (int64_t)r * ldc + c) =
                        make_uint2(f2tf(v0), f2tf(v1));
                } else {
                    *(float2*)(C + (int64_t)r * ldc + c) = make_float2(v0, v1);
                }
            }
        }
    }
}

// ---------------- host orchestration ----------------------------------------
static inline dim3 ggrid(int M, int N, int batch, int bm) {
    return dim3((unsigned)((N + 127) / 128), (unsigned)((M + bm - 1) / bm), (unsigned)batch);
}

extern "C" void kernel_launch(void* const* d_in, const int* in_sizes, int n_in,
                              void* d_out, int out_size)
{
    const int*   idx    = (const int*)  d_in[0];
    const float* tok_w  = (const float*)d_in[1];
    const float* pos    = (const float*)d_in[2];
    const float* ln1_s  = (const float*)d_in[3];
    const float* ln1_b  = (const float*)d_in[4];
    const float* wq     = (const float*)d_in[5];
    const float* wk     = (const float*)d_in[6];
    const float* wv     = (const float*)d_in[7];
    const float* wo     = (const float*)d_in[8];
    const float* bo     = (const float*)d_in[9];
    const float* ln2_s  = (const float*)d_in[10];
    const float* ln2_b  = (const float*)d_in[11];
    const float* w1     = (const float*)d_in[12];
    const float* b1     = (const float*)d_in[13];
    const float* w2     = (const float*)d_in[14];
    const float* b2     = (const float*)d_in[15];
    const float* lnf_s  = (const float*)d_in[16];
    const float* lnf_b  = (const float*)d_in[17];
    const float* head_w = (const float*)d_in[18];
    const float* head_b = (const float*)d_in[19];
    float* out = (float*)d_out;

    float* x;
    uint32_t *h, *q, *k, *v, *o, *ff;
    uint32_t *cwq, *cwk, *cwv, *cwo, *cw1, *cw2, *chw;
    cudaGetSymbolAddress((void**)&x,   g_x);
    cudaGetSymbolAddress((void**)&h,   g_h);
    cudaGetSymbolAddress((void**)&q,   g_q);
    cudaGetSymbolAddress((void**)&k,   g_k);
    cudaGetSymbolAddress((void**)&v,   g_v);
    cudaGetSymbolAddress((void**)&o,   g_o);
    cudaGetSymbolAddress((void**)&ff,  g_ff);
    cudaGetSymbolAddress((void**)&cwq, g_wq);
    cudaGetSymbolAddress((void**)&cwk, g_wk);
    cudaGetSymbolAddress((void**)&cwv, g_wv);
    cudaGetSymbolAddress((void**)&cwo, g_wo);
    cudaGetSymbolAddress((void**)&cw1, g_w1);
    cudaGetSymbolAddress((void**)&cw2, g_w2);
    cudaGetSymbolAddress((void**)&chw, g_hw);

    const int M = Bq * Tq;                  // 2048
    const int flashSmem = FL_SMEM_WORDS * 4;
    const int gemmSmem128 = 4 * (128 * 20 + 16 * 132) * 4;  // 74752 B
    const int gemmSmem64  = 4 * ( 64 * 20 + 16 * 132) * 4;  // 54272 B
    cudaFuncSetAttribute(flash_kernel,
        cudaFuncAttributeMaxDynamicSharedMemorySize, flashSmem);
    cudaFuncSetAttribute(gemm_tc<128>,
        cudaFuncAttributeMaxDynamicSharedMemorySize, gemmSmem128);
    cudaFuncSetAttribute(gemm_tc<64>,
        cudaFuncAttributeMaxDynamicSharedMemorySize, gemmSmem64);

    // ---- convert weights to tf32 (once per launch) ----
    {
        int nE  = Lq * Eq * Eq  / 4;
        int nF  = Lq * Eq * FFq / 4;
        int nH  = Eq * Vq / 4;
        cvt_kernel<<<(nE + 255) / 256, 256>>>(wq, cwq, nE);
        cvt_kernel<<<(nE + 255) / 256, 256>>>(wk, cwk, nE);
        cvt_kernel<<<(nE + 255) / 256, 256>>>(wv, cwv, nE);
        cvt_kernel<<<(nE + 255) / 256, 256>>>(wo, cwo, nE);
        cvt_kernel<<<(nF + 255) / 256, 256>>>(w1, cw1, nF);
        cvt_kernel<<<(nF + 255) / 256, 256>>>(w2, cw2, nF);
        cvt_kernel<<<(nH + 255) / 256, 256>>>(head_w, chw, nH);
    }

    // embedding
    embed_kernel<<<(M * Eq / 4 + 255) / 256, 256>>>(idx, tok_w, pos, x);

    for (int l = 0; l < Lq; l++) {
        const uint32_t* Wq = cwq + (int64_t)l * Eq * Eq;
        const uint32_t* Wk = cwk + (int64_t)l * Eq * Eq;
        const uint32_t* Wv = cwv + (int64_t)l * Eq * Eq;
        const uint32_t* Wo = cwo + (int64_t)l * Eq * Eq;
        const uint32_t* W1 = cw1 + (int64_t)l * Eq * FFq;
        const uint32_t* W2 = cw2 + (int64_t)l * FFq * Eq;

        // ln1 -> h (tf32)
        ln_kernel<<<M, 256>>>(x, h, ln1_s + l * Eq, ln1_b + l * Eq);

        // fused q/k/v projections, outputs tf32
        gemm_tc<128><<<ggrid(M, Eq, 3, 128), 256, gemmSmem128>>>(h, Wq, (float*)q,
            M, Eq, Eq, Eq, Eq, Eq,
            nullptr, nullptr, 0, 1,
            Wk, (float*)k, Wv, (float*)v);

        // fused flash attention -> o (tf32)
        flash_kernel<<<dim3(Tq / 128, Bq * Hq), 256, flashSmem>>>(q, k, v, o);

        // x = x + o @ Wo + bo  (fp32 out)
        gemm_tc<64><<<ggrid(M, Eq, 1, 64), 256, gemmSmem64>>>(o, Wo, x,
            M, Eq, Eq, Eq, Eq, Eq,
            bo + l * Eq, x, 0, 0,
            nullptr, nullptr, nullptr, nullptr);

        // ln2 -> h (tf32)
        ln_kernel<<<M, 256>>>(x, h, ln2_s + l * Eq, ln2_b + l * Eq);

        // ff = relu(h @ W1 + b1)  (tf32 out)
        gemm_tc<128><<<ggrid(M, FFq, 1, 128), 256, gemmSmem128>>>(h, W1, (float*)ff,
            M, FFq, Eq, Eq, FFq, FFq,
            b1 + l * FFq, nullptr, 1, 1,
            nullptr, nullptr, nullptr, nullptr);

        // x = x + ff @ W2 + b2  (fp32 out)
        gemm_tc<64><<<ggrid(M, Eq, 1, 64), 256, gemmSmem64>>>(ff, W2, x,
            M, Eq, FFq, FFq, Eq, Eq,
            b2 + l * Eq, x, 0, 0,
            nullptr, nullptr, nullptr, nullptr);
    }

    // final layernorm -> h (tf32)
    ln_kernel<<<M, 256>>>(x, h, lnf_s, lnf_b);

    // logits = h @ head_w + head_b (fp32 out)
    gemm_tc<128><<<ggrid(M, Vq, 1, 128), 256, gemmSmem128>>>(h, chw, out,
        M, Vq, Eq, Eq, Vq, Vq,
        head_b, nullptr, 0, 0,
        nullptr, nullptr, nullptr, nullptr);
}